// round 1
// baseline (speedup 1.0000x reference)
#include <cuda_runtime.h>
#include <math.h>

#define WS_      14
#define NTOK     196      // WS*WS
#define NH_      12
#define HD_      64
#define DIM_     768
#define NWIN     200      // 8 * 5 * 5
#define BH_      2400     // NWIN * NH_
#define MROWS    39200    // NWIN * NTOK
#define IMGHW    64
#define QKV_N    2304

// ---- scratch (static device globals; no allocations allowed) ----
__device__ float g_q [BH_ * NTOK * HD_];   // [win*12+h][196][64]
__device__ float g_k [BH_ * NTOK * HD_];
__device__ float g_v [BH_ * NTOK * HD_];
__device__ float g_ao[MROWS * DIM_];       // attention out [win][tok][h*64+d]

// =====================================================================
// GEMM 1: qkv = gather(x) @ qkv_w^T + qkv_b   (M=39200, K=768, N=2304)
// BM=128 BN=128 BK=16, 256 threads, 8x8 microtile.
// A-tile gather does the window partition + zero padding on the fly.
// Epilogue splits into g_q/g_k/g_v with [bh][tok][d] layout.
// =====================================================================
__global__ __launch_bounds__(256)
void qkv_gemm(const float* __restrict__ x, const float* __restrict__ w,
              const float* __restrict__ bias)
{
    __shared__ float As[16][132];
    __shared__ float Bs[16][132];
    const int tid = threadIdx.x;
    const int m0 = blockIdx.x * 128;
    const int n0 = blockIdx.y * 128;
    const int tx = tid & 15;
    const int ty = tid >> 4;

    // precompute gather base for the 2 A-rows this thread loads
    int abase[2];
#pragma unroll
    for (int i = 0; i < 2; i++) {
        int lin = tid + 256 * i;
        int row = lin >> 2;
        int gm  = m0 + row;
        int base = -1;
        if (gm < MROWS) {
            int wdw = gm / NTOK, t = gm - wdw * NTOK;
            int b  = wdw / 25,  wi = wdw - b * 25;
            int wh = wi / 5,    ww = wi - wh * 5;
            int th = t / WS_,   tw = t - th * WS_;
            int y  = wh * WS_ + th;
            int xc = ww * WS_ + tw;
            if (y < IMGHW && xc < IMGHW)
                base = ((b * IMGHW + y) * IMGHW + xc) * DIM_;
        }
        abase[i] = base;
    }

    float acc[8][8];
#pragma unroll
    for (int i = 0; i < 8; i++)
#pragma unroll
        for (int j = 0; j < 8; j++) acc[i][j] = 0.f;

    for (int k0 = 0; k0 < DIM_; k0 += 16) {
#pragma unroll
        for (int i = 0; i < 2; i++) {
            int lin = tid + 256 * i;
            int row = lin >> 2;
            int kq  = (lin & 3) * 4;
            float4 v = make_float4(0.f, 0.f, 0.f, 0.f);
            if (abase[i] >= 0)
                v = *(const float4*)(x + abase[i] + k0 + kq);
            As[kq + 0][row] = v.x; As[kq + 1][row] = v.y;
            As[kq + 2][row] = v.z; As[kq + 3][row] = v.w;
        }
#pragma unroll
        for (int i = 0; i < 2; i++) {
            int lin = tid + 256 * i;
            int row = lin >> 2;
            int kq  = (lin & 3) * 4;
            float4 v = *(const float4*)(w + (n0 + row) * DIM_ + k0 + kq);
            Bs[kq + 0][row] = v.x; Bs[kq + 1][row] = v.y;
            Bs[kq + 2][row] = v.z; Bs[kq + 3][row] = v.w;
        }
        __syncthreads();
#pragma unroll
        for (int kk = 0; kk < 16; kk++) {
            float a[8], b[8];
            float4 t0 = *(const float4*)&As[kk][ty * 8];
            float4 t1 = *(const float4*)&As[kk][ty * 8 + 4];
            a[0]=t0.x; a[1]=t0.y; a[2]=t0.z; a[3]=t0.w;
            a[4]=t1.x; a[5]=t1.y; a[6]=t1.z; a[7]=t1.w;
            float4 u0 = *(const float4*)&Bs[kk][tx * 8];
            float4 u1 = *(const float4*)&Bs[kk][tx * 8 + 4];
            b[0]=u0.x; b[1]=u0.y; b[2]=u0.z; b[3]=u0.w;
            b[4]=u1.x; b[5]=u1.y; b[6]=u1.z; b[7]=u1.w;
#pragma unroll
            for (int i = 0; i < 8; i++)
#pragma unroll
                for (int j = 0; j < 8; j++)
                    acc[i][j] = fmaf(a[i], b[j], acc[i][j]);
        }
        __syncthreads();
    }

#pragma unroll
    for (int i = 0; i < 8; i++) {
        int gm = m0 + ty * 8 + i;
        if (gm >= MROWS) continue;
        int wdw = gm / NTOK, t = gm - wdw * NTOK;
#pragma unroll
        for (int j = 0; j < 8; j++) {
            int gn = n0 + tx * 8 + j;
            float c = acc[i][j] + bias[gn];
            int which = gn / DIM_;
            int r = gn - which * DIM_;
            int h = r >> 6, d = r & 63;
            int idx = ((wdw * NH_ + h) * NTOK + t) * HD_ + d;
            float* dst = (which == 0) ? g_q : ((which == 1) ? g_k : g_v);
            dst[idx] = c;
        }
    }
}

// =====================================================================
// Fused attention per (window, head): scores + rel-pos bias + softmax
// + attn@V.  One block (8 warps) per bh; K/V staged in dynamic smem.
// =====================================================================
#define KS_STRIDE 68
#define ATTN_SMEM_FLOATS (NTOK*KS_STRIDE + NTOK*HD_ + 8*HD_ + 8*NTOK + 8*16 + 8*16)
#define ATTN_SMEM_BYTES  (ATTN_SMEM_FLOATS * 4)

__global__ __launch_bounds__(256)
void attn_kernel(const float* __restrict__ rph, const float* __restrict__ rpw)
{
    extern __shared__ float sm[];
    float* ks  = sm;                          // [196][68]
    float* vs  = ks  + NTOK * KS_STRIDE;      // [196][64]
    float* qb  = vs  + NTOK * HD_;            // [8][64]
    float* ps  = qb  + 8 * HD_;               // [8][196]
    float* rh  = ps  + 8 * NTOK;              // [8][16]
    float* rw  = rh  + 8 * 16;                // [8][16]

    const int bh   = blockIdx.x;
    const int tid  = threadIdx.x;
    const int lane = tid & 31;
    const int warp = tid >> 5;
    const float* q = g_q + bh * (NTOK * HD_);
    const float* k = g_k + bh * (NTOK * HD_);
    const float* v = g_v + bh * (NTOK * HD_);

    for (int i = tid; i < NTOK * HD_; i += 256) {
        int j = i >> 6, d = i & 63;
        ks[j * KS_STRIDE + d] = k[i];
        vs[i] = v[i];
    }
    __syncthreads();

    const float scale = 0.125f;  // 64^-0.5
    float* qw  = qb + warp * HD_;
    float* rhw = rh + warp * 16;
    float* rww = rw + warp * 16;
    float* pw  = ps + warp * NTOK;

    for (int qi = warp; qi < NTOK; qi += 8) {
        qw[lane]      = q[qi * HD_ + lane];
        qw[lane + 32] = q[qi * HD_ + 32 + lane];
        __syncwarp();

        int qh = qi / WS_, qwc = qi - qh * WS_;
        // rel-pos bias partial dots: rel_h[kh] = q . rel_pos_h[qh-kh+13]
        if (lane < WS_) {
            const float* r = rph + (qh - lane + WS_ - 1) * HD_;
            float s = 0.f;
#pragma unroll
            for (int d = 0; d < HD_; d++) s = fmaf(qw[d], __ldg(r + d), s);
            rhw[lane] = s;
        } else if (lane >= 16 && lane < 16 + WS_) {
            int kw = lane - 16;
            const float* r = rpw + (qwc - kw + WS_ - 1) * HD_;
            float s = 0.f;
#pragma unroll
            for (int d = 0; d < HD_; d++) s = fmaf(qw[d], __ldg(r + d), s);
            rww[kw] = s;
        }
        __syncwarp();

        // scores for keys j = lane + 32c
        float sc[7];
        const float4* q4 = (const float4*)qw;
#pragma unroll
        for (int c = 0; c < 7; c++) {
            int j = lane + 32 * c;
            sc[c] = -INFINITY;
            if (j < NTOK) {
                const float4* k4 = (const float4*)(ks + j * KS_STRIDE);
                float s = 0.f;
#pragma unroll
                for (int d4 = 0; d4 < 16; d4++) {
                    float4 a = q4[d4], b = k4[d4];
                    s = fmaf(a.x, b.x, s); s = fmaf(a.y, b.y, s);
                    s = fmaf(a.z, b.z, s); s = fmaf(a.w, b.w, s);
                }
                int kh = j / WS_, kwc = j - kh * WS_;
                sc[c] = s * scale + rhw[kh] + rww[kwc];
            }
        }

        // softmax (warp-wide over 196 keys)
        float mx = -INFINITY;
#pragma unroll
        for (int c = 0; c < 7; c++) mx = fmaxf(mx, sc[c]);
#pragma unroll
        for (int off = 16; off > 0; off >>= 1)
            mx = fmaxf(mx, __shfl_xor_sync(0xffffffffu, mx, off));
        float sum = 0.f;
#pragma unroll
        for (int c = 0; c < 7; c++) {
            int j = lane + 32 * c;
            if (j < NTOK) {
                float p = __expf(sc[c] - mx);
                sum += p;
                pw[j] = p;
            }
        }
#pragma unroll
        for (int off = 16; off > 0; off >>= 1)
            sum += __shfl_xor_sync(0xffffffffu, sum, off);
        __syncwarp();
        float inv = 1.f / sum;

        // out[d] = sum_j p[j] * v[j][d];  each lane owns d = 2*lane, 2*lane+1
        float a0 = 0.f, a1 = 0.f;
        const float2* v2base = (const float2*)vs;
#pragma unroll 4
        for (int j = 0; j < NTOK; j++) {
            float p = pw[j];
            float2 vv = v2base[j * 32 + lane];
            a0 = fmaf(p, vv.x, a0);
            a1 = fmaf(p, vv.y, a1);
        }
        int wdw = bh / NH_, h = bh - wdw * NH_;
        float2* o = (float2*)(g_ao + (wdw * NTOK + qi) * DIM_ + h * HD_);
        o[lane] = make_float2(a0 * inv, a1 * inv);
        __syncwarp();
    }
}

// =====================================================================
// GEMM 2: out = g_ao @ proj_w^T + proj_b, scattered with un-partition
// + crop into d_out [8,64,64,768].  M=39200, K=768, N=768.
// =====================================================================
__global__ __launch_bounds__(256)
void proj_gemm(const float* __restrict__ w, const float* __restrict__ bias,
               float* __restrict__ out)
{
    __shared__ float As[16][132];
    __shared__ float Bs[16][132];
    const int tid = threadIdx.x;
    const int m0 = blockIdx.x * 128;
    const int n0 = blockIdx.y * 128;
    const int tx = tid & 15;
    const int ty = tid >> 4;

    int abase[2];
#pragma unroll
    for (int i = 0; i < 2; i++) {
        int lin = tid + 256 * i;
        int row = lin >> 2;
        int gm  = m0 + row;
        abase[i] = (gm < MROWS) ? gm * DIM_ : -1;
    }

    float acc[8][8];
#pragma unroll
    for (int i = 0; i < 8; i++)
#pragma unroll
        for (int j = 0; j < 8; j++) acc[i][j] = 0.f;

    for (int k0 = 0; k0 < DIM_; k0 += 16) {
#pragma unroll
        for (int i = 0; i < 2; i++) {
            int lin = tid + 256 * i;
            int row = lin >> 2;
            int kq  = (lin & 3) * 4;
            float4 v = make_float4(0.f, 0.f, 0.f, 0.f);
            if (abase[i] >= 0)
                v = *(const float4*)(g_ao + abase[i] + k0 + kq);
            As[kq + 0][row] = v.x; As[kq + 1][row] = v.y;
            As[kq + 2][row] = v.z; As[kq + 3][row] = v.w;
        }
#pragma unroll
        for (int i = 0; i < 2; i++) {
            int lin = tid + 256 * i;
            int row = lin >> 2;
            int kq  = (lin & 3) * 4;
            float4 v = *(const float4*)(w + (n0 + row) * DIM_ + k0 + kq);
            Bs[kq + 0][row] = v.x; Bs[kq + 1][row] = v.y;
            Bs[kq + 2][row] = v.z; Bs[kq + 3][row] = v.w;
        }
        __syncthreads();
#pragma unroll
        for (int kk = 0; kk < 16; kk++) {
            float a[8], b[8];
            float4 t0 = *(const float4*)&As[kk][ty * 8];
            float4 t1 = *(const float4*)&As[kk][ty * 8 + 4];
            a[0]=t0.x; a[1]=t0.y; a[2]=t0.z; a[3]=t0.w;
            a[4]=t1.x; a[5]=t1.y; a[6]=t1.z; a[7]=t1.w;
            float4 u0 = *(const float4*)&Bs[kk][tx * 8];
            float4 u1 = *(const float4*)&Bs[kk][tx * 8 + 4];
            b[0]=u0.x; b[1]=u0.y; b[2]=u0.z; b[3]=u0.w;
            b[4]=u1.x; b[5]=u1.y; b[6]=u1.z; b[7]=u1.w;
#pragma unroll
            for (int i = 0; i < 8; i++)
#pragma unroll
                for (int j = 0; j < 8; j++)
                    acc[i][j] = fmaf(a[i], b[j], acc[i][j]);
        }
        __syncthreads();
    }

    // epilogue: un-partition + crop scatter
#pragma unroll
    for (int i = 0; i < 8; i++) {
        int gm = m0 + ty * 8 + i;
        if (gm >= MROWS) continue;
        int wdw = gm / NTOK, t = gm - wdw * NTOK;
        int b  = wdw / 25,  wi = wdw - b * 25;
        int wh = wi / 5,    ww = wi - wh * 5;
        int th = t / WS_,   tw = t - th * WS_;
        int y  = wh * WS_ + th;
        int xc = ww * WS_ + tw;
        if (y >= IMGHW || xc >= IMGHW) continue;
        float* orow = out + ((b * IMGHW + y) * IMGHW + xc) * DIM_;
#pragma unroll
        for (int j = 0; j < 8; j++) {
            int gn = n0 + tx * 8 + j;
            orow[gn] = acc[i][j] + bias[gn];
        }
    }
}

// =====================================================================
extern "C" void kernel_launch(void* const* d_in, const int* in_sizes, int n_in,
                              void* d_out, int out_size)
{
    const float* x      = (const float*)d_in[0];
    const float* qkv_w  = (const float*)d_in[1];
    const float* qkv_b  = (const float*)d_in[2];
    const float* proj_w = (const float*)d_in[3];
    const float* proj_b = (const float*)d_in[4];
    const float* rph    = (const float*)d_in[5];
    const float* rpw    = (const float*)d_in[6];
    float* out = (float*)d_out;

    cudaFuncSetAttribute(attn_kernel,
                         cudaFuncAttributeMaxDynamicSharedMemorySize,
                         ATTN_SMEM_BYTES);

    dim3 g1((MROWS + 127) / 128, QKV_N / 128);
    qkv_gemm<<<g1, 256>>>(x, qkv_w, qkv_b);

    attn_kernel<<<BH_, 256, ATTN_SMEM_BYTES>>>(rph, rpw);

    dim3 g2((MROWS + 127) / 128, DIM_ / 128);
    proj_gemm<<<g2, 256>>>(proj_w, proj_b, out);
}